// round 1
// baseline (speedup 1.0000x reference)
#include <cuda_runtime.h>
#include <math.h>

// Problem constants
#define N_NODES 8000
#define T_DIM   12
#define F_DIM   5
#define NT      (N_NODES * T_DIM)      // 96000
#define NBLK_A  80
#define CHUNK_A (N_NODES / NBLK_A)     // 100

// Partial sums from reduction kernel: per block, 120 values
//   [0..59]  : lhs_tf partial, index j = t*5 + f   (= sum_n x[n,t,f]*U1[n])
//   [60..119]: M2 partial,     index j-60 = f2*12+t (= sum_n U2[f2,n]*rhs[n,t])
__device__ float g_part[NBLK_A][128];

__global__ void __launch_bounds__(128)
reduce_kernel(const float* __restrict__ x,
              const float* __restrict__ U1,
              const float* __restrict__ U2,
              const float* __restrict__ U3)
{
    const int j  = threadIdx.x;
    const int n0 = blockIdx.x * CHUNK_A;
    float acc = 0.f;

    if (j < 60) {
        // lhs_tf[t,f]: contiguous, coalesced across threads 0..59 per n
        for (int i = 0; i < CHUNK_A; i++) {
            const int n = n0 + i;
            acc += x[n * 60 + j] * U1[n];
        }
    } else if (j < 120) {
        const int jj = j - 60;
        const int f2 = jj / 12;
        const int t  = jj % 12;
        float u3[5];
        #pragma unroll
        for (int f = 0; f < 5; f++) u3[f] = U3[f];
        for (int i = 0; i < CHUNK_A; i++) {
            const int n = n0 + i;
            float r = 0.f;
            #pragma unroll
            for (int f = 0; f < 5; f++)
                r += x[n * 60 + t * 5 + f] * u3[f];   // L1/L2 hits (same lines as lhs warps)
            acc += U2[f2 * N_NODES + n] * r;          // broadcast within 12-thread group
        }
    }
    g_part[blockIdx.x][j] = acc;   // 120..127 write 0, never read
}

__global__ void __launch_bounds__(256)
main_kernel(const float* __restrict__ x,
            const float* __restrict__ be,
            const float* __restrict__ Ve,
            const float* __restrict__ w,     // conv2_w: (5,5,1,3) flat o*15+i*3+k
            const float* __restrict__ bias,  // conv2_b: (5,)
            float* __restrict__ out)
{
    __shared__ float sLhs[60];        // [t*5+f]
    __shared__ float sM2[60];         // [f2*12+t]
    __shared__ float sS[12][12];
    __shared__ float sE[12][12];
    __shared__ float sAt[12][12];     // At2[t1][t2]
    __shared__ float sW[75];
    __shared__ float sB[5];

    const int tid = threadIdx.x;

    // --- Reduce partials (every block does this redundantly; deterministic, ~cheap) ---
    if (tid < 120) {
        float s = 0.f;
        #pragma unroll 8
        for (int b = 0; b < NBLK_A; b++) s += g_part[b][tid];
        if (tid < 60) sLhs[tid] = s;
        else          sM2[tid - 60] = s;
    }
    if (tid < 75) sW[tid] = w[tid];
    if (tid < 5)  sB[tid] = bias[tid];
    __syncthreads();

    // --- prod = lhs_tf @ M2 ; S = sigmoid(prod + be) ---
    if (tid < 144) {
        const int t1 = tid / 12, t2 = tid % 12;
        float p = 0.f;
        #pragma unroll
        for (int f = 0; f < 5; f++) p += sLhs[t1 * 5 + f] * sM2[f * 12 + t2];
        p += be[tid];
        sS[t1][t2] = 1.f / (1.f + expf(-p));
    }
    __syncthreads();

    // --- E = Ve @ S ---
    if (tid < 144) {
        const int t1 = tid / 12, t2 = tid % 12;
        float e = 0.f;
        #pragma unroll
        for (int k = 0; k < 12; k++) e += Ve[t1 * 12 + k] * sS[k][t2];
        sE[t1][t2] = e;
    }
    __syncthreads();

    // --- At2 = softmax(E, axis=0 over t1) i.e. column softmax ---
    if (tid < 12) {
        const int t2 = tid;
        float mx = -1e30f;
        #pragma unroll
        for (int k = 0; k < 12; k++) mx = fmaxf(mx, sE[k][t2]);
        float tmp[12], den = 0.f;
        #pragma unroll
        for (int k = 0; k < 12; k++) { tmp[k] = expf(sE[k][t2] - mx); den += tmp[k]; }
        const float inv = 1.f / den;
        #pragma unroll
        for (int k = 0; k < 12; k++) sAt[k][t2] = tmp[k] * inv;
    }
    __syncthreads();

    // --- Per-node: x2 = x @ At2 (over time), then 1x3 conv over t ---
    const int n = blockIdx.x * blockDim.x + tid;
    if (n >= N_NODES) return;

    __align__(16) float buf[60];                       // x[n, t', f] : idx t'*5+f
    const float4* xp = (const float4*)(x + n * 60);    // 240B, 16B aligned
    #pragma unroll
    for (int i = 0; i < 15; i++) ((float4*)buf)[i] = xp[i];

    float x2[5][12];
    #pragma unroll
    for (int f = 0; f < 5; f++) {
        #pragma unroll
        for (int t = 0; t < 12; t++) {
            float a = 0.f;
            #pragma unroll
            for (int tp = 0; tp < 12; tp++)
                a += buf[tp * 5 + f] * sAt[tp][t];     // shared broadcast
            x2[f][t] = a;
        }
    }

    #pragma unroll
    for (int o = 0; o < 5; o++) {
        float yr[12];
        #pragma unroll
        for (int t = 0; t < 12; t++) {
            float a = sB[o];
            #pragma unroll
            for (int fi = 0; fi < 5; fi++) {
                #pragma unroll
                for (int k = 0; k < 3; k++) {
                    const int tt = t + k - 1;
                    if (tt >= 0 && tt < 12)
                        a += sW[o * 15 + fi * 3 + k] * x2[fi][tt];
                }
            }
            yr[t] = a;
        }
        // Raw-reshape output: flat idx = o*N*T + n*T + t  (48B per plane, 16B aligned)
        float4* op = (float4*)(out + o * NT + n * 12);
        op[0] = make_float4(yr[0], yr[1], yr[2],  yr[3]);
        op[1] = make_float4(yr[4], yr[5], yr[6],  yr[7]);
        op[2] = make_float4(yr[8], yr[9], yr[10], yr[11]);
    }
}

extern "C" void kernel_launch(void* const* d_in, const int* in_sizes, int n_in,
                              void* d_out, int out_size)
{
    // metadata order: x, adj, U1_1, U2_1, U3_1, be_1, Ve_1,
    //                 U1_2, U2_2, U3_2, be_2, Ve_2,
    //                 conv1_w, conv1_b, conv2_w, conv2_b, W_hgc, b_hgc
    const float* x    = (const float*)d_in[0];
    const float* U1_2 = (const float*)d_in[7];
    const float* U2_2 = (const float*)d_in[8];
    const float* U3_2 = (const float*)d_in[9];
    const float* be_2 = (const float*)d_in[10];
    const float* Ve_2 = (const float*)d_in[11];
    const float* c2w  = (const float*)d_in[14];
    const float* c2b  = (const float*)d_in[15];
    float* out = (float*)d_out;

    // The hyperbolic branch (At1/conv1/adj-graph-conv) contributes exactly 0.0*finite
    // to the output -> skipped entirely.
    reduce_kernel<<<NBLK_A, 128>>>(x, U1_2, U2_2, U3_2);
    main_kernel<<<(N_NODES + 255) / 256, 256>>>(x, be_2, Ve_2, c2w, c2b, out);
}

// round 2
// speedup vs baseline: 1.1932x; 1.1932x over previous
#include <cuda_runtime.h>
#include <math.h>

#define N_NODES 8000
#define T_DIM   12
#define NT      (N_NODES * T_DIM)      // 96000
#define NBLK_A  80
#define CHUNK_A (N_NODES / NBLK_A)     // 100
#define SUBG    4                      // sub-groups inside reduce block
#define SUBCH   (CHUNK_A / SUBG)       // 25

#define NODES_PER_BLK 64
#define MAIN_THREADS  320              // 5 * 64
#define MAIN_BLOCKS   (N_NODES / NODES_PER_BLK)   // 125

// Partial sums: per block, 120 values
//   [0..59]  : lhs_tf partial, j = t*5+f      (= sum_n x[n,t,f]*U1[n])
//   [60..119]: M2 partial,     j-60 = f2*12+t (= sum_n U2[f2,n]*rhs[n,t])
__device__ float g_part[NBLK_A][128];

__global__ void __launch_bounds__(SUBG * 128)
reduce_kernel(const float* __restrict__ x,
              const float* __restrict__ U1,
              const float* __restrict__ U2,
              const float* __restrict__ U3)
{
    __shared__ float sAcc[SUBG][128];
    const int j = threadIdx.x & 127;       // 0..127 (use <120)
    const int g = threadIdx.x >> 7;        // 0..3
    const int n0 = blockIdx.x * CHUNK_A + g * SUBCH;

    float acc = 0.f;
    if (j < 60) {
        #pragma unroll 5
        for (int i = 0; i < SUBCH; i++) {
            const int n = n0 + i;
            acc += x[n * 60 + j] * U1[n];
        }
    } else if (j < 120) {
        const int jj = j - 60;
        const int f2 = jj / 12;
        const int t  = jj % 12;
        float u3[5];
        #pragma unroll
        for (int f = 0; f < 5; f++) u3[f] = U3[f];
        #pragma unroll 5
        for (int i = 0; i < SUBCH; i++) {
            const int n = n0 + i;
            float r = 0.f;
            #pragma unroll
            for (int f = 0; f < 5; f++) r += x[n * 60 + t * 5 + f] * u3[f];
            acc += U2[f2 * N_NODES + n] * r;
        }
    }
    sAcc[g][j] = acc;
    __syncthreads();
    if (g == 0) {
        // deterministic fixed-order combine
        float s = sAcc[0][j] + sAcc[1][j] + sAcc[2][j] + sAcc[3][j];
        g_part[blockIdx.x][j] = s;
    }
}

__global__ void __launch_bounds__(MAIN_THREADS)
main_kernel(const float* __restrict__ x,
            const float* __restrict__ be,
            const float* __restrict__ Ve,
            const float* __restrict__ w,     // conv2_w: (5,5,1,3) flat o*15+i*3+k
            const float* __restrict__ bias,  // conv2_b: (5,)
            float* __restrict__ out)
{
    __shared__ float sX[NODES_PER_BLK][61];        // x[n_local][t'*5+f], pad 61 (odd stride)
    __shared__ float sX2[5][NODES_PER_BLK * 13];   // x2[f][n_local*13 + t], stride 13
    __shared__ float sLhs[60];
    __shared__ float sM2[60];
    __shared__ float sS[12][12];
    __shared__ float sE[12][12];
    __shared__ float sAt[12][12];
    __shared__ float sW[75];
    __shared__ float sB[5];

    const int tid = threadIdx.x;
    const int n0  = blockIdx.x * NODES_PER_BLK;

    // ---- Coalesced load of this block's 64x60 floats (960 float4) into shared ----
    {
        const float4* xp = (const float4*)(x + n0 * 60);
        #pragma unroll
        for (int r = 0; r < 3; r++) {
            const int j = tid + r * MAIN_THREADS;   // 0..959
            float4 v = xp[j];
            const int n  = j / 15;                  // 15 float4 per node row
            const int c  = (j % 15) * 4;
            float* d = &sX[n][c];
            d[0] = v.x; d[1] = v.y; d[2] = v.z; d[3] = v.w;
        }
    }

    // ---- Redundant final reduce of partials (120 threads) ----
    if (tid < 120) {
        float s = 0.f;
        #pragma unroll 8
        for (int b = 0; b < NBLK_A; b++) s += g_part[b][tid];
        if (tid < 60) sLhs[tid] = s;
        else          sM2[tid - 60] = s;
    }
    if (tid >= 128 && tid < 203) sW[tid - 128] = w[tid - 128];
    if (tid >= 224 && tid < 229) sB[tid - 224] = bias[tid - 224];
    __syncthreads();

    // ---- prod = lhs_tf @ M2 ; S = sigmoid(prod + be) ----
    if (tid < 144) {
        const int t1 = tid / 12, t2 = tid % 12;
        float p = 0.f;
        #pragma unroll
        for (int f = 0; f < 5; f++) p += sLhs[t1 * 5 + f] * sM2[f * 12 + t2];
        p += be[tid];
        sS[t1][t2] = 1.f / (1.f + expf(-p));
    }
    __syncthreads();

    // ---- E = Ve @ S ----
    if (tid < 144) {
        const int t1 = tid / 12, t2 = tid % 12;
        float e = 0.f;
        #pragma unroll
        for (int k = 0; k < 12; k++) e += Ve[t1 * 12 + k] * sS[k][t2];
        sE[t1][t2] = e;
    }
    __syncthreads();

    // ---- At2 = column softmax over t1 ----
    if (tid < 12) {
        const int t2 = tid;
        float mx = -1e30f;
        #pragma unroll
        for (int k = 0; k < 12; k++) mx = fmaxf(mx, sE[k][t2]);
        float tmp[12], den = 0.f;
        #pragma unroll
        for (int k = 0; k < 12; k++) { tmp[k] = expf(sE[k][t2] - mx); den += tmp[k]; }
        const float inv = 1.f / den;
        #pragma unroll
        for (int k = 0; k < 12; k++) sAt[k][t2] = tmp[k] * inv;
    }
    __syncthreads();

    // ---- Phase B: thread (f, n_local) computes x2[f][n][0..11] ----
    {
        const int f  = tid / NODES_PER_BLK;   // 0..4
        const int nl = tid % NODES_PER_BLK;
        float xr[12];
        #pragma unroll
        for (int tp = 0; tp < 12; tp++) xr[tp] = sX[nl][tp * 5 + f];
        float* dst = &sX2[f][nl * 13];
        #pragma unroll
        for (int t = 0; t < 12; t++) {
            float a = 0.f;
            #pragma unroll
            for (int tp = 0; tp < 12; tp++) a += xr[tp] * sAt[tp][t];
            dst[t] = a;
        }
    }
    __syncthreads();

    // ---- Phase C: thread (o, n_local) computes conv plane + coalesced store ----
    {
        const int o  = tid / NODES_PER_BLK;   // 0..4
        const int nl = tid % NODES_PER_BLK;
        float wr[15];
        #pragma unroll
        for (int i = 0; i < 15; i++) wr[i] = sW[o * 15 + i];
        const float b0 = sB[o];

        float yr[12];
        #pragma unroll
        for (int t = 0; t < 12; t++) yr[t] = b0;
        #pragma unroll
        for (int fi = 0; fi < 5; fi++) {
            const float* s = &sX2[fi][nl * 13];
            float v[12];
            #pragma unroll
            for (int t = 0; t < 12; t++) v[t] = s[t];
            const float w0 = wr[fi * 3 + 0], w1 = wr[fi * 3 + 1], w2 = wr[fi * 3 + 2];
            #pragma unroll
            for (int t = 0; t < 12; t++) {
                float a = w1 * v[t];
                if (t > 0)  a += w0 * v[t - 1];
                if (t < 11) a += w2 * v[t + 1];
                yr[t] += a;
            }
        }
        // raw-reshape output: flat = o*N*T + n*T + t
        float4* op = (float4*)(out + o * NT + (n0 + nl) * 12);
        op[0] = make_float4(yr[0], yr[1], yr[2],  yr[3]);
        op[1] = make_float4(yr[4], yr[5], yr[6],  yr[7]);
        op[2] = make_float4(yr[8], yr[9], yr[10], yr[11]);
    }
}

extern "C" void kernel_launch(void* const* d_in, const int* in_sizes, int n_in,
                              void* d_out, int out_size)
{
    // metadata order: x, adj, U1_1, U2_1, U3_1, be_1, Ve_1,
    //                 U1_2, U2_2, U3_2, be_2, Ve_2,
    //                 conv1_w, conv1_b, conv2_w, conv2_b, W_hgc, b_hgc
    const float* x    = (const float*)d_in[0];
    const float* U1_2 = (const float*)d_in[7];
    const float* U2_2 = (const float*)d_in[8];
    const float* U3_2 = (const float*)d_in[9];
    const float* be_2 = (const float*)d_in[10];
    const float* Ve_2 = (const float*)d_in[11];
    const float* c2w  = (const float*)d_in[14];
    const float* c2b  = (const float*)d_in[15];
    float* out = (float*)d_out;

    // Hyperbolic branch contributes exactly 0.0*finite -> skipped.
    reduce_kernel<<<NBLK_A, SUBG * 128>>>(x, U1_2, U2_2, U3_2);
    main_kernel<<<MAIN_BLOCKS, MAIN_THREADS>>>(x, be_2, Ve_2, c2w, c2b, out);
}

// round 3
// speedup vs baseline: 1.2718x; 1.0658x over previous
#include <cuda_runtime.h>
#include <math.h>

#define N_NODES 8000
#define T_DIM   12
#define NT      (N_NODES * T_DIM)      // 96000

#define NODES_PER_BLK 64
#define NTHREADS      320              // 5 * 64
#define NBLOCKS       (N_NODES / NODES_PER_BLK)   // 125  (<=148 SMs: all co-resident)

// Transposed partials: g_partT[j][b]  (slots b=125..127 never written -> stay 0.0
// from static zero-init, giving a fixed-length deterministic float4 reduction)
__device__ float    g_partT[120][128];
__device__ unsigned g_arrive;          // monotonic epoch counter (never reset)

__global__ void __launch_bounds__(NTHREADS)
fused_kernel(const float* __restrict__ x,
             const float* __restrict__ U1,
             const float* __restrict__ U2,   // (5, 8000) row-major
             const float* __restrict__ U3,
             const float* __restrict__ be,
             const float* __restrict__ Ve,
             const float* __restrict__ w,    // conv2_w (5,5,1,3) flat o*15+i*3+k
             const float* __restrict__ bias, // conv2_b (5,)
             float* __restrict__ out)
{
    __shared__ float sX [NODES_PER_BLK][61];      // x[nl][t*5+f], pad 61 (odd)
    __shared__ float sRhs[NODES_PER_BLK][13];     // rhs[nl][t] = sum_f x*U3
    __shared__ float sX2[5][NODES_PER_BLK * 13];  // x2[f][nl*13+t]
    __shared__ float sU1[NODES_PER_BLK];
    __shared__ float sU2[5][NODES_PER_BLK];
    __shared__ float sU3[5];
    __shared__ float sLhs[60];
    __shared__ float sM2[60];
    __shared__ float sS[12][12];
    __shared__ float sE[12][12];
    __shared__ float sAt[12][12];
    __shared__ float sW[75];
    __shared__ float sB[5];

    const int tid = threadIdx.x;
    const int b   = blockIdx.x;
    const int n0  = b * NODES_PER_BLK;

    // ---- Coalesced load of this block's 64x60 floats (960 float4) into shared ----
    {
        const float4* xp = (const float4*)(x + n0 * 60);
        #pragma unroll
        for (int r = 0; r < 3; r++) {
            const int j = tid + r * NTHREADS;     // 0..959
            float4 v = xp[j];
            const int n = j / 15;
            const int c = (j % 15) * 4;
            float* d = &sX[n][c];
            d[0] = v.x; d[1] = v.y; d[2] = v.z; d[3] = v.w;
        }
    }
    // small parameter tiles (independent loads, overlap with x)
    if (tid < NODES_PER_BLK) sU1[tid] = U1[n0 + tid];
    if (tid < 5)             sU3[tid] = U3[tid];
    {
        const int f2 = tid / NODES_PER_BLK;       // 0..4
        const int nl = tid % NODES_PER_BLK;
        sU2[f2][nl] = U2[f2 * N_NODES + n0 + nl];
    }
    if (tid >= 64 && tid < 139) sW[tid - 64] = w[tid - 64];
    if (tid >= 160 && tid < 165) sB[tid - 160] = bias[tid - 160];
    __syncthreads();

    // ---- rhs[nl][t] = sum_f sX[nl][t*5+f] * U3[f]   (768 entries, 320 threads) ----
    for (int j = tid; j < NODES_PER_BLK * 12; j += NTHREADS) {
        const int nl = j / 12, t = j % 12;
        float r = 0.f;
        #pragma unroll
        for (int f = 0; f < 5; f++) r += sX[nl][t * 5 + f] * sU3[f];
        sRhs[nl][t] = r;
    }
    __syncthreads();

    // ---- This block's partials over its 64 nodes ----
    //   j<60  : lhs_p[j=t*5+f]  = sum_nl sX[nl][j] * U1[nl]
    //   60..119: M2_p[f2*12+t]  = sum_nl U2[f2][nl] * rhs[nl][t]
    if (tid < 120) {
        float acc = 0.f;
        if (tid < 60) {
            #pragma unroll 8
            for (int nl = 0; nl < NODES_PER_BLK; nl++)
                acc += sX[nl][tid] * sU1[nl];
        } else {
            const int jj = tid - 60;
            const int f2 = jj / 12, t = jj % 12;
            #pragma unroll 8
            for (int nl = 0; nl < NODES_PER_BLK; nl++)
                acc += sU2[f2][nl] * sRhs[nl][t];
        }
        g_partT[tid][b] = acc;       // scattered 4B store, cheap
        __threadfence();             // make visible at L2 (gpu scope)
    }
    __syncthreads();

    // ---- Grid barrier: monotonic epoch counter (all 125 blocks co-resident) ----
    if (tid == 0) {
        unsigned old = atomicAdd(&g_arrive, 1u);
        unsigned target = (old / (unsigned)NBLOCKS + 1u) * (unsigned)NBLOCKS;
        volatile unsigned* va = &g_arrive;
        while (*va < target) { }
        __threadfence();             // acquire: invalidate L1 before partial reads
    }
    __syncthreads();

    // ---- Combine all partials: 32 independent float4 L2 loads, fixed order ----
    if (tid < 120) {
        const float4* p = (const float4*)g_partT[tid];
        float s = 0.f;
        #pragma unroll
        for (int i = 0; i < 32; i++) {
            float4 v = __ldcg(p + i);        // L2 (coherent) — slots 125..127 are 0
            s += v.x + v.y + v.z + v.w;
        }
        if (tid < 60) sLhs[tid] = s;
        else          sM2[tid - 60] = s;
    }
    __syncthreads();

    // ---- prod = lhs_tf @ M2 ; S = sigmoid(prod + be) ----
    if (tid < 144) {
        const int t1 = tid / 12, t2 = tid % 12;
        float p = 0.f;
        #pragma unroll
        for (int f = 0; f < 5; f++) p += sLhs[t1 * 5 + f] * sM2[f * 12 + t2];
        p += be[tid];
        sS[t1][t2] = 1.f / (1.f + expf(-p));
    }
    __syncthreads();

    // ---- E = Ve @ S ----
    if (tid < 144) {
        const int t1 = tid / 12, t2 = tid % 12;
        float e = 0.f;
        #pragma unroll
        for (int k = 0; k < 12; k++) e += Ve[t1 * 12 + k] * sS[k][t2];
        sE[t1][t2] = e;
    }
    __syncthreads();

    // ---- At2 = column softmax over t1 ----
    if (tid < 12) {
        const int t2 = tid;
        float mx = -1e30f;
        #pragma unroll
        for (int k = 0; k < 12; k++) mx = fmaxf(mx, sE[k][t2]);
        float tmp[12], den = 0.f;
        #pragma unroll
        for (int k = 0; k < 12; k++) { tmp[k] = expf(sE[k][t2] - mx); den += tmp[k]; }
        const float inv = 1.f / den;
        #pragma unroll
        for (int k = 0; k < 12; k++) sAt[k][t2] = tmp[k] * inv;
    }
    __syncthreads();

    // ---- Phase B: thread (f, nl) computes x2[f][nl][0..11] ----
    {
        const int f  = tid / NODES_PER_BLK;
        const int nl = tid % NODES_PER_BLK;
        float xr[12];
        #pragma unroll
        for (int tp = 0; tp < 12; tp++) xr[tp] = sX[nl][tp * 5 + f];
        float* dst = &sX2[f][nl * 13];
        #pragma unroll
        for (int t = 0; t < 12; t++) {
            float a = 0.f;
            #pragma unroll
            for (int tp = 0; tp < 12; tp++) a += xr[tp] * sAt[tp][t];
            dst[t] = a;
        }
    }
    __syncthreads();

    // ---- Phase C: thread (o, nl) computes conv plane + coalesced 48B store ----
    {
        const int o  = tid / NODES_PER_BLK;
        const int nl = tid % NODES_PER_BLK;
        float wr[15];
        #pragma unroll
        for (int i = 0; i < 15; i++) wr[i] = sW[o * 15 + i];
        const float b0 = sB[o];

        float yr[12];
        #pragma unroll
        for (int t = 0; t < 12; t++) yr[t] = b0;
        #pragma unroll
        for (int fi = 0; fi < 5; fi++) {
            const float* s = &sX2[fi][nl * 13];
            float v[12];
            #pragma unroll
            for (int t = 0; t < 12; t++) v[t] = s[t];
            const float w0 = wr[fi * 3 + 0], w1 = wr[fi * 3 + 1], w2 = wr[fi * 3 + 2];
            #pragma unroll
            for (int t = 0; t < 12; t++) {
                float a = w1 * v[t];
                if (t > 0)  a += w0 * v[t - 1];
                if (t < 11) a += w2 * v[t + 1];
                yr[t] += a;
            }
        }
        // raw-reshape output: flat = o*N*T + n*T + t
        float4* op = (float4*)(out + o * NT + (n0 + nl) * 12);
        op[0] = make_float4(yr[0], yr[1], yr[2],  yr[3]);
        op[1] = make_float4(yr[4], yr[5], yr[6],  yr[7]);
        op[2] = make_float4(yr[8], yr[9], yr[10], yr[11]);
    }
}

extern "C" void kernel_launch(void* const* d_in, const int* in_sizes, int n_in,
                              void* d_out, int out_size)
{
    // metadata order: x, adj, U1_1, U2_1, U3_1, be_1, Ve_1,
    //                 U1_2, U2_2, U3_2, be_2, Ve_2,
    //                 conv1_w, conv1_b, conv2_w, conv2_b, W_hgc, b_hgc
    const float* x    = (const float*)d_in[0];
    const float* U1_2 = (const float*)d_in[7];
    const float* U2_2 = (const float*)d_in[8];
    const float* U3_2 = (const float*)d_in[9];
    const float* be_2 = (const float*)d_in[10];
    const float* Ve_2 = (const float*)d_in[11];
    const float* c2w  = (const float*)d_in[14];
    const float* c2b  = (const float*)d_in[15];
    float* out = (float*)d_out;

    // Hyperbolic branch contributes exactly 0.0*finite -> skipped entirely.
    fused_kernel<<<NBLOCKS, NTHREADS>>>(x, U1_2, U2_2, U3_2, be_2, Ve_2, c2w, c2b, out);
}